// round 9
// baseline (speedup 1.0000x reference)
#include <cuda_runtime.h>
#include <cuda_bf16.h>

#define BLK        128
#define GRID       456                   // 3 blocks/SM x 152 SMs -> single persistent wave
#define TILE_ROWS  128
#define WROWS      32                    // rows per warp
#define CHUNK      20                    // time-steps per chunk (100 = 5 x 20, no tail)
#define C4MAX      5                     // float4 per row per chunk
#define S4         5                     // float4 row stride in smem (conflict-free, no pad)
#define NSLOT      3
#define WBUF_F4    (WROWS * S4)          // 160 float4 per (slot, array, warp)
#define SMEM_BYTES (NSLOT * 2 * 4 * WBUF_F4 * 16)   // 61440 B -> 3 blocks/SM

// Scratch (alloc-free rule). g_tick wraps to 0 every launch -> graph-replay safe.
__device__ float g_partials[GRID];
__device__ unsigned int g_tick;

__device__ __forceinline__ void cp16(unsigned s, const void* g) {
    asm volatile("cp.async.cg.shared.global [%0], [%1], 16;" :: "r"(s), "l"(g));
}
__device__ __forceinline__ void cp_commit() {
    asm volatile("cp.async.commit_group;");
}
template <int N> __device__ __forceinline__ void cp_wait() {
    asm volatile("cp.async.wait_group %0;" :: "n"(N));
}

__global__ void __launch_bounds__(BLK) spike_loss_kernel(
    const float* __restrict__ outputs,
    const float* __restrict__ target,
    const int* __restrict__ n_steps_p,
    const int* __restrict__ tau_p,
    long long total_elems,
    float* __restrict__ out)
{
    extern __shared__ float4 sm[];

    const int   T       = *n_steps_p;
    const float inv_tau = 1.0f / (float)(*tau_p);
    const float decay   = 1.0f - inv_tau;
    const long long rows = (T > 0) ? total_elems / (long long)T : 0;

    const int tid  = threadIdx.x;
    const int wid  = tid >> 5;
    const int lane = tid & 31;
    float acc = 0.0f;

    if (T >= 4 && (T & 3) == 0) {
        // ===== fast path: per-warp 3-slot cp.async pipeline, issue-before-compute =====
        const unsigned sm_base = (unsigned)__cvta_generic_to_shared(sm);
        const int nch   = (T + CHUNK - 1) / CHUNK;
        const int last4 = (T - (nch - 1) * CHUNK + 3) >> 2;   // float4s in last chunk (1..5)

        const long long wrow_base   = (long long)blockIdx.x * TILE_ROWS + wid * WROWS;
        const long long tile_stride = (long long)GRID * TILE_ROWS;

        long long ntiles = 0;
        {
            const long long first = (long long)blockIdx.x * TILE_ROWS;
            if (first < rows)
                ntiles = (rows - first + tile_stride - 1) / tile_stride;
        }
        const long long nci = ntiles * nch;

        // smem base (float4 units) for (slot, arr) of this warp
        auto buf_f4 = [&](int slot, int arr) -> unsigned {
            return (unsigned)(((slot * 2 + arr) * 4 + wid) * WBUF_F4);
        };

        auto load_chunk = [&](long long ci, int slot) {
            const long long row0 = wrow_base + (ci / nch) * tile_stride;
            const int k  = (int)(ci % nch);
            const int t0 = k * CHUNK;
            const int c4 = (k == nch - 1) ? last4 : C4MAX;
            const unsigned st = sm_base + buf_f4(slot, 0) * 16;
            const unsigned so = sm_base + buf_f4(slot, 1) * 16;
            if (c4 == C4MAX) {
                #pragma unroll
                for (int it = 0; it < C4MAX; ++it) {      // 32 rows x 5 f4 / 32 lanes
                    const int fid = it * 32 + lane;
                    const int r = fid / C4MAX, j = fid - r * C4MAX;
                    const long long row = row0 + r;
                    if (row < rows) {
                        const long long g = row * (long long)T + t0 + 4 * j;
                        const unsigned off = (unsigned)((r * S4 + j) * 16);
                        cp16(st + off, target  + g);
                        cp16(so + off, outputs + g);
                    }
                }
            } else {
                for (int fid = lane; fid < WROWS * c4; fid += 32) {
                    const int r = fid / c4, j = fid - r * c4;
                    const long long row = row0 + r;
                    if (row < rows) {
                        const long long g = row * (long long)T + t0 + 4 * j;
                        const unsigned off = (unsigned)((r * S4 + j) * 16);
                        cp16(st + off, target  + g);
                        cp16(so + off, outputs + g);
                    }
                }
            }
            cp_commit();
        };

        // prologue (per warp)
        if (nci > 0) load_chunk(0, 0);
        if (nci > 1) load_chunk(1, 1);

        float syn = 0.0f;
        int slot = 0;

        for (long long ci = 0; ci < nci; ++ci) {
            if (ci + 1 < nci) cp_wait<1>(); else cp_wait<0>();
            __syncwarp();        // all lanes past compute of ci-1; slot (ci+2)%3 free

            // issue next load BEFORE compute -> load stream never waits on compute
            if (ci + 2 < nci) {
                int nslot = slot + 2; if (nslot >= NSLOT) nslot -= NSLOT;
                load_chunk(ci + 2, nslot);
            }

            const long long row0 = wrow_base + (ci / nch) * tile_stride;
            const int k  = (int)(ci % nch);
            const int c4 = (k == nch - 1) ? last4 : C4MAX;
            if (k == 0) syn = 0.0f;

            if (row0 + lane < rows) {
                const float4* xt = sm + buf_f4(slot, 0) + lane * S4;
                const float4* xo = sm + buf_f4(slot, 1) + lane * S4;
                if (c4 == C4MAX) {
                    #pragma unroll
                    for (int j = 0; j < C4MAX; ++j) {
                        const float4 x = xt[j];
                        const float4 o = xo[j];
                        float e;
                        syn = fmaf(syn, decay, x.x); e = fmaf(-syn, inv_tau, o.x); acc = fmaf(e, e, acc);
                        syn = fmaf(syn, decay, x.y); e = fmaf(-syn, inv_tau, o.y); acc = fmaf(e, e, acc);
                        syn = fmaf(syn, decay, x.z); e = fmaf(-syn, inv_tau, o.z); acc = fmaf(e, e, acc);
                        syn = fmaf(syn, decay, x.w); e = fmaf(-syn, inv_tau, o.w); acc = fmaf(e, e, acc);
                    }
                } else {
                    for (int j = 0; j < c4; ++j) {
                        const float4 x = xt[j];
                        const float4 o = xo[j];
                        float e;
                        syn = fmaf(syn, decay, x.x); e = fmaf(-syn, inv_tau, o.x); acc = fmaf(e, e, acc);
                        syn = fmaf(syn, decay, x.y); e = fmaf(-syn, inv_tau, o.y); acc = fmaf(e, e, acc);
                        syn = fmaf(syn, decay, x.z); e = fmaf(-syn, inv_tau, o.z); acc = fmaf(e, e, acc);
                        syn = fmaf(syn, decay, x.w); e = fmaf(-syn, inv_tau, o.w); acc = fmaf(e, e, acc);
                    }
                }
            }
            if (++slot >= NSLOT) slot = 0;
        }
    } else if (T > 0) {
        // ===== generic fallback: scalar thread-per-row =====
        const long long gtid = (long long)blockIdx.x * BLK + tid;
        for (long long row = gtid; row < rows; row += (long long)GRID * BLK) {
            const float* tg = target  + row * (long long)T;
            const float* op = outputs + row * (long long)T;
            float syn = 0.0f;
            for (int t = 0; t < T; ++t) {
                syn = fmaf(syn, decay, tg[t]);
                const float e = fmaf(-syn, inv_tau, op[t]);
                acc = fmaf(e, e, acc);
            }
        }
    }

    // ---- block reduce ----
    #pragma unroll
    for (int off = 16; off > 0; off >>= 1)
        acc += __shfl_xor_sync(0xFFFFFFFF, acc, off);

    __shared__ float wsum[BLK / 32];
    if (lane == 0) wsum[wid] = acc;
    __syncthreads();

    __shared__ bool is_last;
    if (tid == 0) {
        float s = 0.0f;
        #pragma unroll
        for (int i = 0; i < BLK / 32; ++i) s += wsum[i];
        g_partials[blockIdx.x] = s;
        __threadfence();
        const unsigned prev = atomicInc(&g_tick, GRID - 1);   // wraps to 0 each launch
        is_last = (prev == GRID - 1);
    }
    __syncthreads();

    if (is_last) {
        double d = 0.0;
        for (int i = tid; i < GRID; i += BLK)
            d += (double)g_partials[i];
        #pragma unroll
        for (int off = 16; off > 0; off >>= 1)
            d += __shfl_xor_sync(0xFFFFFFFF, d, off);
        __shared__ double dsum[BLK / 32];
        if (lane == 0) dsum[wid] = d;
        __syncthreads();
        if (tid == 0) {
            double t = 0.0;
            #pragma unroll
            for (int i = 0; i < BLK / 32; ++i) t += dsum[i];
            out[0] = (float)(0.5 * t);
        }
    }
}

extern "C" void kernel_launch(void* const* d_in, const int* in_sizes, int n_in,
                              void* d_out, int out_size)
{
    const float* outputs = (const float*)d_in[0];
    const float* target  = (const float*)d_in[1];
    const int*   n_steps = (const int*)d_in[2];
    const int*   tau_s   = (const int*)d_in[3];
    float*       out     = (float*)d_out;

    const long long total = (long long)in_sizes[0];

    cudaFuncSetAttribute(spike_loss_kernel,
                         cudaFuncAttributeMaxDynamicSharedMemorySize, SMEM_BYTES);
    spike_loss_kernel<<<GRID, BLK, SMEM_BYTES>>>(outputs, target, n_steps, tau_s, total, out);
}